// round 1
// baseline (speedup 1.0000x reference)
#include <cuda_runtime.h>
#include <math.h>

#define NMAX 1024
#define MAXSH 729
#define EPS2 1e-16f
#define COEF 14.399645478425668

struct EwaldParams {
    float eta;
    float inv_s2eta;   // 1/(sqrt(2)*eta)
    float cut2_real;
    float cut2_recip;
    float vol;
    float self_c;      // -sqrt(2/pi)/eta
    float recip[9];    // recip matrix rows (2*pi*inv(cell)^T)
    int   nsh;         // number of real-space shift vectors
    int   two_nr1;     // 2*nshift_recip+1
    int   K;           // two_nr1^3
    int   nr;          // nshift_recip
};

__device__ EwaldParams g_p;
__device__ double g_acc;
__device__ float g_shifts[MAXSH * 3];

__global__ void setup_kernel(const float* __restrict__ cell,
                             const int* __restrict__ nshift_real,
                             const int* __restrict__ nshift_recip, int n)
{
    // single thread
    double c[9];
    for (int i = 0; i < 9; i++) c[i] = (double)cell[i];
    double det = c[0]*(c[4]*c[8]-c[5]*c[7])
               - c[1]*(c[3]*c[8]-c[5]*c[6])
               + c[2]*(c[3]*c[7]-c[4]*c[6]);
    double vol = fabs(det);
    const double PI = 3.14159265358979323846;
    const double TWO_PI = 2.0 * PI;
    double eta = pow(vol*vol/(double)n, 1.0/6.0) / sqrt(TWO_PI);
    double s2log = sqrt(-2.0*log(1e-8));
    double cutr = s2log*eta;
    double cutk = s2log/eta;
    double id = 1.0/det;
    double inv[9];
    inv[0] =  (c[4]*c[8]-c[5]*c[7])*id;
    inv[1] = -(c[1]*c[8]-c[2]*c[7])*id;
    inv[2] =  (c[1]*c[5]-c[2]*c[4])*id;
    inv[3] = -(c[3]*c[8]-c[5]*c[6])*id;
    inv[4] =  (c[0]*c[8]-c[2]*c[6])*id;
    inv[5] = -(c[0]*c[5]-c[2]*c[3])*id;
    inv[6] =  (c[3]*c[7]-c[4]*c[6])*id;
    inv[7] = -(c[0]*c[7]-c[1]*c[6])*id;
    inv[8] =  (c[0]*c[4]-c[1]*c[3])*id;
    // recip[i][j] = 2*pi * inv[j][i]  (recip = 2*pi*inv(cell)^T)
    for (int i = 0; i < 3; i++)
        for (int j = 0; j < 3; j++)
            g_p.recip[i*3 + j] = (float)(TWO_PI * inv[j*3 + i]);
    g_p.eta        = (float)eta;
    g_p.inv_s2eta  = (float)(1.0/(sqrt(2.0)*eta));
    g_p.cut2_real  = (float)(cutr*cutr);
    g_p.cut2_recip = (float)(cutk*cutk);
    g_p.vol        = (float)vol;
    g_p.self_c     = (float)(-sqrt(2.0/PI)/eta);

    int nrr = nshift_real[0];
    int two = 2*nrr + 1;
    int cnt = two*two*two;
    if (cnt > MAXSH) cnt = MAXSH;
    g_p.nsh = cnt;
    int idx = 0;
    for (int a = -nrr; a <= nrr; a++)
        for (int b = -nrr; b <= nrr; b++)
            for (int cc = -nrr; cc <= nrr; cc++) {
                if (idx < cnt) {
                    g_shifts[idx*3+0] = (float)(a*c[0] + b*c[3] + cc*c[6]);
                    g_shifts[idx*3+1] = (float)(a*c[1] + b*c[4] + cc*c[7]);
                    g_shifts[idx*3+2] = (float)(a*c[2] + b*c[5] + cc*c[8]);
                }
                idx++;
            }
    int nrk = nshift_recip[0];
    g_p.nr = nrk;
    g_p.two_nr1 = 2*nrk + 1;
    g_p.K = g_p.two_nr1 * g_p.two_nr1 * g_p.two_nr1;
    g_acc = 0.0;
}

// Real-space + self: upper triangle (i<=j), off-diagonal weighted 2x.
__global__ void __launch_bounds__(256) real_kernel(
    const float* __restrict__ pos,
    const float* __restrict__ q,
    const float* __restrict__ sig_table,
    const int*   __restrict__ spec,
    int n)
{
    __shared__ float sx[NMAX], sy[NMAX], sz[NMAX], sq[NMAX], ssig[NMAX];
    __shared__ float ssh[MAXSH*3];
    __shared__ double sred[256];

    int cnt = g_p.nsh;
    for (int i = threadIdx.x; i < n; i += blockDim.x) {
        sx[i] = pos[i*3+0]; sy[i] = pos[i*3+1]; sz[i] = pos[i*3+2];
        sq[i] = q[i];
        ssig[i] = sig_table[spec[i]];
    }
    for (int i = threadIdx.x; i < cnt*3; i += blockDim.x) ssh[i] = g_shifts[i];
    __syncthreads();

    const float inv_s2eta = g_p.inv_s2eta;
    const float cut2 = g_p.cut2_real;
    const float self_c = g_p.self_c;
    const float SQRTPI = 1.7724538509055160f;

    long long T = (long long)n*(n+1)/2;
    long long stride = (long long)gridDim.x * blockDim.x;
    double tacc = 0.0;

    for (long long p = (long long)blockIdx.x*blockDim.x + threadIdx.x; p < T; p += stride) {
        double tn = 2.0*(double)n + 1.0;
        double disc = tn*tn - 8.0*(double)p;
        int i = (int)((tn - sqrt(disc)) * 0.5);
        if (i < 0) i = 0;
        if (i >= n) i = n - 1;
        long long off = (long long)i*n - (long long)i*(i-1)/2;
        while (p < off) { i--; off = (long long)i*n - (long long)i*(i-1)/2; }
        while (p >= off + (long long)(n - i)) { off += (n - i); i++; }
        int j = i + (int)(p - off);

        float xi = sx[i], yi = sy[i], zi = sz[i];
        float dx0 = sx[j]-xi, dy0 = sy[j]-yi, dz0 = sz[j]-zi;
        float gi = ssig[i], gj = ssig[j];
        float inv_s2gam = rsqrtf(2.f*(gi*gi + gj*gj));

        float acc = 0.f;
        for (int s = 0; s < cnt; s++) {
            float dx = dx0 + ssh[s*3+0];
            float dy = dy0 + ssh[s*3+1];
            float dz = dz0 + ssh[s*3+2];
            float d2 = fmaf(dx, dx, fmaf(dy, dy, dz*dz));
            if (d2 > EPS2 && d2 < cut2) {
                float dist = sqrtf(d2);
                float v = (erfcf(dist*inv_s2eta) - erfcf(dist*inv_s2gam)) / dist;
                acc += v;
            }
        }
        float w = sq[i]*sq[j];
        if (i == j) acc += self_c + 1.f/(SQRTPI*gi);
        else        w *= 2.f;
        tacc += (double)(w * acc);
    }

    sred[threadIdx.x] = tacc;
    __syncthreads();
    for (int s = 128; s > 0; s >>= 1) {
        if (threadIdx.x < s) sred[threadIdx.x] += sred[threadIdx.x + s];
        __syncthreads();
    }
    if (threadIdx.x == 0) atomicAdd(&g_acc, 0.5*COEF*sred[0]);
}

// Reciprocal space: one warp per k-vector, structure-factor reduction.
__global__ void __launch_bounds__(256) recip_kernel(
    const float* __restrict__ pos,
    const float* __restrict__ q,
    int n)
{
    __shared__ float sx[NMAX], sy[NMAX], sz[NMAX], sq[NMAX];
    __shared__ double sred[8];
    for (int i = threadIdx.x; i < n; i += blockDim.x) {
        sx[i] = pos[i*3+0]; sy[i] = pos[i*3+1]; sz[i] = pos[i*3+2];
        sq[i] = q[i];
    }
    __syncthreads();

    int lane  = threadIdx.x & 31;
    int warp  = threadIdx.x >> 5;
    int gwarp = (blockIdx.x*blockDim.x + threadIdx.x) >> 5;
    int nwarps = (gridDim.x*blockDim.x) >> 5;

    int two = g_p.two_nr1, nr = g_p.nr, K = g_p.K;
    float R00=g_p.recip[0], R01=g_p.recip[1], R02=g_p.recip[2];
    float R10=g_p.recip[3], R11=g_p.recip[4], R12=g_p.recip[5];
    float R20=g_p.recip[6], R21=g_p.recip[7], R22=g_p.recip[8];
    float cut2 = g_p.cut2_recip;
    float eta2h = 0.5f * g_p.eta * g_p.eta;

    double wacc = 0.0;
    for (int k = gwarp; k < K; k += nwarps) {
        int t = k;
        int a  = t % two - nr; t /= two;
        int b  = t % two - nr;
        int c2 = t / two - nr;
        float kx = a*R00 + b*R10 + c2*R20;
        float ky = a*R01 + b*R11 + c2*R21;
        float kz = a*R02 + b*R12 + c2*R22;
        float kl2 = kx*kx + ky*ky + kz*kz;
        if (!(kl2 > EPS2 && kl2 < cut2)) continue;

        float Sc = 0.f, Ss = 0.f;
        for (int i = lane; i < n; i += 32) {
            float th = fmaf(kx, sx[i], fmaf(ky, sy[i], kz*sz[i]));
            float sn, cs;
            __sincosf(th, &sn, &cs);
            float qi = sq[i];
            Sc = fmaf(qi, cs, Sc);
            Ss = fmaf(qi, sn, Ss);
        }
        #pragma unroll
        for (int o = 16; o > 0; o >>= 1) {
            Sc += __shfl_down_sync(0xffffffffu, Sc, o);
            Ss += __shfl_down_sync(0xffffffffu, Ss, o);
        }
        if (lane == 0) {
            float wk = __expf(-eta2h*kl2) / kl2;
            wacc += (double)(wk * (Sc*Sc + Ss*Ss));
        }
    }

    // only lane 0 of each warp holds a nonzero partial
    if (lane == 0) sred[warp] = wacc;
    __syncthreads();
    if (threadIdx.x == 0) {
        double s = 0.0;
        int nw = blockDim.x >> 5;
        for (int w2 = 0; w2 < nw; w2++) s += sred[w2];
        double pref = 0.5 * COEF * 4.0 * 3.14159265358979323846 / (double)g_p.vol;
        atomicAdd(&g_acc, pref * s);
    }
}

__global__ void finalize_kernel(float* out)
{
    out[0] = (float)g_acc;
}

extern "C" void kernel_launch(void* const* d_in, const int* in_sizes, int n_in,
                              void* d_out, int out_size)
{
    const float* pos     = (const float*)d_in[0];
    const float* cell    = (const float*)d_in[1];
    const float* charges = (const float*)d_in[2];
    const float* sigt    = (const float*)d_in[3];
    const int*   spec    = (const int*)d_in[4];
    const int*   nsr     = (const int*)d_in[5];
    const int*   nsk     = (const int*)d_in[6];
    int n = in_sizes[0] / 3;

    setup_kernel<<<1, 1>>>(cell, nsr, nsk, n);

    long long T = (long long)n*(n+1)/2;
    int blocks = (int)((T + 255) / 256);
    if (blocks > 8192) blocks = 8192;
    if (blocks < 1) blocks = 1;
    real_kernel<<<blocks, 256>>>(pos, charges, sigt, spec, n);

    recip_kernel<<<616, 256>>>(pos, charges, n);

    finalize_kernel<<<1, 1>>>((float*)d_out);
}

// round 2
// speedup vs baseline: 1.1536x; 1.1536x over previous
#include <cuda_runtime.h>
#include <math.h>

#define NMAXA 1024
#define MAXSH 729
#define EPS2 1e-16f
#define COEF 14.399645478425668
#define SQRTPI 1.7724538509055160f

__device__ double g_acc = 0.0;
__device__ unsigned int g_done = 0;

struct Params {
    float R[9];     // reciprocal matrix rows: k = a*R0 + b*R1 + c*R2
    float cf[9];    // cell (float)
    float inv_s2eta, cut2r, cut2k, eta2h, self_c, pref4;
    int   nsh, nr, nrows;
    long long T;
    long long urecip, utotal;
};

__global__ void __launch_bounds__(256) ewald_fused_kernel(
    const float* __restrict__ pos,
    const float* __restrict__ cell,
    const float* __restrict__ q,
    const float* __restrict__ sigt,
    const int*   __restrict__ spec,
    const int*   __restrict__ nsr,
    const int*   __restrict__ nsk,
    float* __restrict__ out,
    int n)
{
    __shared__ float sx[NMAXA], sy[NMAXA], sz[NMAXA], sq[NMAXA], ssig[NMAXA];
    __shared__ float4 ssh4[MAXSH];
    __shared__ float uc[NMAXA], us[NMAXA];
    __shared__ double sred[256];
    __shared__ Params P;

    const int tid = threadIdx.x;

    // ---- per-block parameter computation (thread 0, fp64) ----
    if (tid == 0) {
        double c[9];
        #pragma unroll
        for (int i = 0; i < 9; i++) c[i] = (double)cell[i];
        double det = c[0]*(c[4]*c[8]-c[5]*c[7])
                   - c[1]*(c[3]*c[8]-c[5]*c[6])
                   + c[2]*(c[3]*c[7]-c[4]*c[6]);
        double vol = fabs(det);
        const double PI_ = 3.14159265358979323846;
        double eta  = pow(vol*vol/(double)n, 1.0/6.0) / sqrt(2.0*PI_);
        double s2lg = sqrt(-2.0*log(1e-8));
        double cutr = s2lg*eta, cutk = s2lg/eta;
        double id = 1.0/det;
        double inv[9];
        inv[0] =  (c[4]*c[8]-c[5]*c[7])*id;
        inv[1] = -(c[1]*c[8]-c[2]*c[7])*id;
        inv[2] =  (c[1]*c[5]-c[2]*c[4])*id;
        inv[3] = -(c[3]*c[8]-c[5]*c[6])*id;
        inv[4] =  (c[0]*c[8]-c[2]*c[6])*id;
        inv[5] = -(c[0]*c[5]-c[2]*c[3])*id;
        inv[6] =  (c[3]*c[7]-c[4]*c[6])*id;
        inv[7] = -(c[0]*c[7]-c[1]*c[6])*id;
        inv[8] =  (c[0]*c[4]-c[1]*c[3])*id;
        #pragma unroll
        for (int i = 0; i < 3; i++)
            #pragma unroll
            for (int j = 0; j < 3; j++)
                P.R[i*3+j] = (float)(2.0*PI_*inv[j*3+i]);
        #pragma unroll
        for (int i = 0; i < 9; i++) P.cf[i] = (float)c[i];
        P.inv_s2eta = (float)(1.0/(sqrt(2.0)*eta));
        P.cut2r     = (float)(cutr*cutr);
        P.cut2k     = (float)(cutk*cutk);
        P.eta2h     = (float)(0.5*eta*eta);
        P.self_c    = (float)(-sqrt(2.0/PI_)/eta);
        P.pref4     = (float)(4.0*PI_/vol);

        int nrr = nsr[0];
        int two = 2*nrr + 1;
        int cnt = two*two*two;
        if (cnt > MAXSH) cnt = MAXSH;
        P.nsh = cnt;

        int nrk = nsk[0];
        P.nr = nrk;
        P.nrows = 1 + nrk + nrk*(2*nrk+1);          // hemisphere (b,c) rows
        P.T = (long long)n*(n+1)/2;
        P.urecip = (P.nrows + 7) / 8;               // 8 warps per block
        P.utotal = P.urecip + (P.T + 255) / 256;
    }

    // ---- cooperative loads ----
    for (int i = tid; i < n; i += 256) {
        sx[i] = pos[i*3+0]; sy[i] = pos[i*3+1]; sz[i] = pos[i*3+2];
        sq[i] = q[i];
        ssig[i] = sigt[spec[i]];
    }
    __syncthreads();

    // per-atom unit phase e^{i phi0}, phi0 = R0 . p
    {
        const float R00=P.R[0], R01=P.R[1], R02=P.R[2];
        for (int i = tid; i < n; i += 256) {
            float ph = R00*sx[i] + R01*sy[i] + R02*sz[i];
            float sn, co; sincosf(ph, &sn, &co);
            uc[i] = co; us[i] = sn;
        }
    }
    // real-space shift vectors
    {
        int nsh = P.nsh;
        int nrr_two = 0;
        // recover two = cbrt(nsh): nsh = two^3 (capped case handled: nsh<=MAXSH)
        while ((nrr_two+1)*(nrr_two+1)*(nrr_two+1) <= nsh) nrr_two++;
        int two = nrr_two;
        int nrr = (two - 1) / 2;
        for (int s = tid; s < nsh; s += 256) {
            int a = s/(two*two) - nrr;
            int r2 = s%(two*two);
            int b = r2/two - nrr;
            int cc = r2%two - nrr;
            float shx = a*P.cf[0] + b*P.cf[3] + cc*P.cf[6];
            float shy = a*P.cf[1] + b*P.cf[4] + cc*P.cf[7];
            float shz = a*P.cf[2] + b*P.cf[5] + cc*P.cf[8];
            ssh4[s] = make_float4(shx, shy, shz, 0.f);
        }
    }
    __syncthreads();

    const float R00=P.R[0],R01=P.R[1],R02=P.R[2];
    const float R10=P.R[3],R11=P.R[4],R12=P.R[5];
    const float R20=P.R[6],R21=P.R[7],R22=P.R[8];
    const float cut2r = P.cut2r, cut2k = P.cut2k;
    const float inv_s2eta = P.inv_s2eta, eta2h = P.eta2h, self_c = P.self_c;
    const int   nr = P.nr, nsh = P.nsh;
    const long long Urec = P.urecip, Utot = P.utotal, T = P.T;

    const int lane = tid & 31, wrp = tid >> 5;

    double racc = 0.0, kacc = 0.0;

    for (long long w = blockIdx.x; w < Utot; w += gridDim.x) {
        if (w < Urec) {
            // ================= RECIPROCAL: one (b,c) row per warp =================
            int row = (int)w*8 + wrp;
            if (row < P.nrows) {
                int b, cc; float wt;
                if (row == 0)          { b = 0;   cc = 0; wt = 1.f; }
                else if (row <= nr)    { b = row; cc = 0; wt = 2.f; }
                else {
                    int t2 = row - 1 - nr, two = 2*nr + 1;
                    cc = t2/two + 1; b = t2%two - nr; wt = 2.f;
                }
                // row feasibility: min over a of |a*R0 + u|^2
                float ux = b*R10 + cc*R20, uy = b*R11 + cc*R21, uz = b*R12 + cc*R22;
                float s00 = R00*R00 + R01*R01 + R02*R02;
                float s0u = R00*ux + R01*uy + R02*uz;
                float uu  = ux*ux + uy*uy + uz*uz;
                float a1f = floorf(-s0u/s00);
                float mink2 = 1e30f;
                #pragma unroll
                for (int t2 = 0; t2 < 2; t2++) {
                    float af = fminf(fmaxf(a1f + t2, (float)(-nr)), (float)nr);
                    mink2 = fminf(mink2, fmaf(af, fmaf(af, s00, 2.f*s0u), uu));
                }
                if (mink2 < cut2k) {
                    if (nr == 8) {
                        // fast path: phase recurrence over a, 17 accumulators
                        float Sc[17], Ss[17];
                        #pragma unroll
                        for (int t2 = 0; t2 < 17; t2++) { Sc[t2]=0.f; Ss[t2]=0.f; }
                        float bf = (float)b, cf2 = (float)cc;
                        for (int i = lane; i < n; i += 32) {
                            float x=sx[i], y=sy[i], z=sz[i], qi=sq[i];
                            float th = bf*(R10*x + R11*y + R12*z)
                                     + cf2*(R20*x + R21*y + R22*z);
                            float sn, co; sincosf(th, &sn, &co);
                            float pr = qi*co, pim = qi*sn;      // P+ (a=0)
                            float mr = pr,  mi = pim;           // P-
                            float ur = uc[i], ui = us[i];
                            Sc[8] += pr; Ss[8] += pim;
                            #pragma unroll
                            for (int a = 1; a <= 8; a++) {
                                float t1 = pr*ur - pim*ui; pim = pr*ui + pim*ur; pr = t1;
                                Sc[8+a] += pr;  Ss[8+a] += pim;
                                float t3 = mr*ur + mi*ui;  mi  = mi*ur - mr*ui;  mr = t3;
                                Sc[8-a] += mr;  Ss[8-a] += mi;
                            }
                        }
                        #pragma unroll
                        for (int t2 = 0; t2 < 17; t2++) {
                            float scv = Sc[t2], ssv = Ss[t2];
                            #pragma unroll
                            for (int o = 16; o > 0; o >>= 1) {
                                scv += __shfl_xor_sync(0xffffffffu, scv, o);
                                ssv += __shfl_xor_sync(0xffffffffu, ssv, o);
                            }
                            if (lane == 0) {
                                float af = (float)(t2 - 8);
                                float kx = af*R00 + ux, ky = af*R01 + uy, kz = af*R02 + uz;
                                float kl2 = kx*kx + ky*ky + kz*kz;
                                if (kl2 > EPS2 && kl2 < cut2k)
                                    kacc += (double)(wt * __expf(-eta2h*kl2) / kl2
                                                     * (scv*scv + ssv*ssv));
                            }
                        }
                    } else {
                        // generic path: direct sincos per k
                        for (int a = -nr; a <= nr; a++) {
                            float af = (float)a;
                            float kx = af*R00 + ux, ky = af*R01 + uy, kz = af*R02 + uz;
                            float kl2 = kx*kx + ky*ky + kz*kz;
                            if (!(kl2 > EPS2 && kl2 < cut2k)) continue;
                            float scv = 0.f, ssv = 0.f;
                            for (int i = lane; i < n; i += 32) {
                                float th = kx*sx[i] + ky*sy[i] + kz*sz[i];
                                float sn, co; sincosf(th, &sn, &co);
                                scv = fmaf(sq[i], co, scv);
                                ssv = fmaf(sq[i], sn, ssv);
                            }
                            #pragma unroll
                            for (int o = 16; o > 0; o >>= 1) {
                                scv += __shfl_xor_sync(0xffffffffu, scv, o);
                                ssv += __shfl_xor_sync(0xffffffffu, ssv, o);
                            }
                            if (lane == 0)
                                kacc += (double)(wt * __expf(-eta2h*kl2) / kl2
                                                 * (scv*scv + ssv*ssv));
                        }
                    }
                }
            }
        } else {
            // ================= REAL: 256 pairs per unit, one per thread =================
            long long p = (w - Urec)*256 + tid;
            if (p < T) {
                // decode upper-triangular (i,j), i<=j
                double tn = 2.0*(double)n + 1.0;
                double disc = tn*tn - 8.0*(double)p;
                int i = (int)((tn - sqrt(disc)) * 0.5);
                if (i < 0) i = 0;
                if (i >= n) i = n - 1;
                long long off = (long long)i*n - (long long)i*(i-1)/2;
                while (p < off) { i--; off = (long long)i*n - (long long)i*(i-1)/2; }
                while (p >= off + (long long)(n - i)) { off += (n - i); i++; }
                int j = i + (int)(p - off);

                float xi = sx[i], yi = sy[i], zi = sz[i];
                float dx0 = sx[j]-xi, dy0 = sy[j]-yi, dz0 = sz[j]-zi;
                float gi = ssig[i], gj = ssig[j];
                float g2 = gi*gi + gj*gj;
                float inv_s2gam = rsqrtf(2.f*g2);
                float gth2 = 46.1f*g2;   // beyond this d^2, erfc(d/(sqrt2*gam)) < 1.2e-11

                float sum = 0.f;
                for (int s0 = 0; s0 < nsh; s0 += 32) {
                    int lim = min(32, nsh - s0);
                    unsigned mask = 0u;
                    for (int t = 0; t < lim; t++) {
                        float4 sv = ssh4[s0 + t];
                        float dx = dx0 + sv.x, dy = dy0 + sv.y, dz = dz0 + sv.z;
                        float d2 = fmaf(dx, dx, fmaf(dy, dy, dz*dz));
                        if (d2 > EPS2 && d2 < cut2r) mask |= (1u << t);
                    }
                    while (mask) {
                        int t = __ffs(mask) - 1; mask &= mask - 1;
                        float4 sv = ssh4[s0 + t];
                        float dx = dx0 + sv.x, dy = dy0 + sv.y, dz = dz0 + sv.z;
                        float d2 = fmaf(dx, dx, fmaf(dy, dy, dz*dz));
                        float dist = sqrtf(d2);
                        float v = erfcf(dist*inv_s2eta);
                        if (d2 < gth2) v -= erfcf(dist*inv_s2gam);
                        sum += v/dist;
                    }
                }
                float wq = sq[i]*sq[j];
                if (i == j) racc += (double)(wq*(sum + self_c + 1.f/(SQRTPI*gi)));
                else        racc += (double)(2.f*wq*sum);
            }
        }
    }

    // ---- block reduction + global accumulation + finalize ----
    double tot = 0.5*COEF*(racc + (double)P.pref4 * kacc);
    sred[tid] = tot;
    __syncthreads();
    for (int s = 128; s > 0; s >>= 1) {
        if (tid < s) sred[tid] += sred[tid + s];
        __syncthreads();
    }
    if (tid == 0) {
        atomicAdd(&g_acc, sred[0]);
        __threadfence();
        unsigned t = atomicAdd(&g_done, 1u);
        if (t == gridDim.x - 1) {
            double v = atomicAdd(&g_acc, 0.0);
            out[0] = (float)v;
            g_acc = 0.0;        // self-clean for next graph replay
            g_done = 0u;
        }
    }
}

extern "C" void kernel_launch(void* const* d_in, const int* in_sizes, int n_in,
                              void* d_out, int out_size)
{
    const float* pos     = (const float*)d_in[0];
    const float* cell    = (const float*)d_in[1];
    const float* charges = (const float*)d_in[2];
    const float* sigt    = (const float*)d_in[3];
    const int*   spec    = (const int*)d_in[4];
    const int*   nsr     = (const int*)d_in[5];
    const int*   nsk     = (const int*)d_in[6];
    int n = in_sizes[0] / 3;

    ewald_fused_kernel<<<592, 256>>>(pos, cell, charges, sigt, spec, nsr, nsk,
                                     (float*)d_out, n);
}

// round 3
// speedup vs baseline: 1.8239x; 1.5810x over previous
#include <cuda_runtime.h>
#include <math.h>

#define NMAXA 1024
#define EPS2 1e-16f
#define COEF 14.399645478425668
#define SQRTPI 1.7724538509055160f
#define TABN 2048
#define TABXMAX 5.0f

__device__ double g_acc = 0.0;
__device__ unsigned int g_done = 0;

struct Params {
    float R[9];       // reciprocal rows: k = a*R0 + b*R1 + c*R2
    float cf[9];      // cell
    float Ld[3], invLd[3];
    float inv_s2eta, cut2r, cut2k, eta2h, self_c, pref4;
    int   nsh, nrr, twoR, nr, nrows2, fastR;
    long long T, Urec, Utot;
};

__global__ void __launch_bounds__(256, 3) ewald_fused_kernel(
    const float* __restrict__ pos,
    const float* __restrict__ cell,
    const float* __restrict__ q,
    const float* __restrict__ sigt,
    const int*   __restrict__ spec,
    const int*   __restrict__ nsr,
    const int*   __restrict__ nsk,
    float* __restrict__ out,
    int n)
{
    __shared__ float sx[NMAXA], sy[NMAXA], sz[NMAXA], sq[NMAXA], ssig[NMAXA];
    __shared__ float uc[NMAXA], us[NMAXA];
    __shared__ float2 stab[TABN];
    __shared__ double sred[256];
    __shared__ Params P;

    const int tid = threadIdx.x;

    if (tid == 0) {
        double c[9];
        #pragma unroll
        for (int i = 0; i < 9; i++) c[i] = (double)cell[i];
        double det = c[0]*(c[4]*c[8]-c[5]*c[7])
                   - c[1]*(c[3]*c[8]-c[5]*c[6])
                   + c[2]*(c[3]*c[7]-c[4]*c[6]);
        double vol = fabs(det);
        const double PI_ = 3.14159265358979323846;
        double eta  = pow(vol*vol/(double)n, 1.0/6.0) / sqrt(2.0*PI_);
        double s2lg = sqrt(-2.0*log(1e-8));
        double cutr = s2lg*eta, cutk = s2lg/eta;
        double id = 1.0/det;
        double inv[9];
        inv[0] =  (c[4]*c[8]-c[5]*c[7])*id;
        inv[1] = -(c[1]*c[8]-c[2]*c[7])*id;
        inv[2] =  (c[1]*c[5]-c[2]*c[4])*id;
        inv[3] = -(c[3]*c[8]-c[5]*c[6])*id;
        inv[4] =  (c[0]*c[8]-c[2]*c[6])*id;
        inv[5] = -(c[0]*c[5]-c[2]*c[3])*id;
        inv[6] =  (c[3]*c[7]-c[4]*c[6])*id;
        inv[7] = -(c[0]*c[7]-c[1]*c[6])*id;
        inv[8] =  (c[0]*c[4]-c[1]*c[3])*id;
        #pragma unroll
        for (int i = 0; i < 3; i++)
            #pragma unroll
            for (int j = 0; j < 3; j++)
                P.R[i*3+j] = (float)(2.0*PI_*inv[j*3+i]);
        #pragma unroll
        for (int i = 0; i < 9; i++) P.cf[i] = (float)c[i];
        P.inv_s2eta = (float)(1.0/(sqrt(2.0)*eta));
        P.cut2r     = (float)(cutr*cutr);
        P.cut2k     = (float)(cutk*cutk);
        P.eta2h     = (float)(0.5*eta*eta);
        P.self_c    = (float)(-sqrt(2.0/PI_)/eta);
        P.pref4     = (float)(4.0*PI_/vol);

        int nrr = nsr[0];
        int two = 2*nrr + 1;
        P.nrr = nrr; P.twoR = two;
        P.nsh = two*two*two;

        // orthorhombic fast-path feasibility
        double offd = fabs(c[1])+fabs(c[2])+fabs(c[3])+fabs(c[5])+fabs(c[6])+fabs(c[7]);
        double dmin = fmin(fabs(c[0]), fmin(fabs(c[4]), fabs(c[8])));
        int fast = (offd < 1e-6*dmin) && (cutr < dmin) && (nrr >= 1);
        P.fastR = fast;
        P.Ld[0] = (float)c[0]; P.Ld[1] = (float)c[4]; P.Ld[2] = (float)c[8];
        P.invLd[0] = (float)(1.0/c[0]); P.invLd[1] = (float)(1.0/c[4]); P.invLd[2] = (float)(1.0/c[8]);

        int nrk = nsk[0];
        P.nr = nrk;
        int nrows = 1 + nrk + nrk*(2*nrk+1);   // hemisphere (b,c) rows
        P.nrows2 = 2*nrows;                     // split into a>=0 / a<0 halves
        P.T = (long long)n*(n+1)/2;
        P.Urec = (P.nrows2 + 7) / 8;
        P.Utot = P.Urec + (P.T + 255) / 256;
    }

    for (int i = tid; i < n; i += 256) {
        sx[i] = pos[i*3+0]; sy[i] = pos[i*3+1]; sz[i] = pos[i*3+2];
        sq[i] = q[i];
        ssig[i] = sigt[spec[i]];
    }
    // erfc lookup table: value + slope
    {
        const float dx = TABXMAX / TABN;
        for (int t = tid; t < TABN; t += 256) {
            float x0 = t * dx;
            float y0 = erfcf(x0);
            float y1 = erfcf(x0 + dx);
            stab[t] = make_float2(y0, y1 - y0);
        }
    }
    __syncthreads();

    // per-atom unit phase e^{i phi0}, phi0 = R0 . p  (for recip recurrence)
    {
        const float R00=P.R[0], R01=P.R[1], R02=P.R[2];
        for (int i = tid; i < n; i += 256) {
            float ph = R00*sx[i] + R01*sy[i] + R02*sz[i];
            float sn, co; sincosf(ph, &sn, &co);
            uc[i] = co; us[i] = sn;
        }
    }
    __syncthreads();

    const float R00=P.R[0],R01=P.R[1],R02=P.R[2];
    const float R10=P.R[3],R11=P.R[4],R12=P.R[5];
    const float R20=P.R[6],R21=P.R[7],R22=P.R[8];
    const float cut2r = P.cut2r, cut2k = P.cut2k;
    const float inv_s2eta = P.inv_s2eta, eta2h = P.eta2h, self_c = P.self_c;
    const int   nr = P.nr;
    const long long Urec = P.Urec, Utot = P.Utot, T = P.T;
    const float TSCALE = (float)TABN / TABXMAX;
    const float TCLAMP = (float)(TABN - 2) + 0.999f;

    const int lane = tid & 31, wrp = tid >> 5;

    double racc = 0.0, kacc = 0.0;

    for (long long w = blockIdx.x; w < Utot; w += gridDim.x) {
        if (w < Urec) {
            // ============ RECIPROCAL: one (b,c,half) per warp ============
            int idx = (int)w*8 + wrp;
            if (idx < P.nrows2) {
                int row = idx >> 1, half = idx & 1;
                int b, cc; float wt;
                if (row == 0)          { b = 0;   cc = 0; wt = 1.f; }
                else if (row <= nr)    { b = row; cc = 0; wt = 2.f; }
                else {
                    int t2 = row - 1 - nr, two = 2*nr + 1;
                    cc = t2/two + 1; b = t2%two - nr; wt = 2.f;
                }
                int alo = half ? -nr : 0;
                int ahi = half ? -1  : nr;
                float ux = b*R10 + cc*R20, uy = b*R11 + cc*R21, uz = b*R12 + cc*R22;
                float s00 = R00*R00 + R01*R01 + R02*R02;
                float s0u = R00*ux + R01*uy + R02*uz;
                float uu  = ux*ux + uy*uy + uz*uz;
                float a1f = floorf(-s0u/s00);
                float mink2 = 1e30f;
                #pragma unroll
                for (int t2 = 0; t2 < 2; t2++) {
                    float af = fminf(fmaxf(a1f + t2, (float)alo), (float)ahi);
                    mink2 = fminf(mink2, fmaf(af, fmaf(af, s00, 2.f*s0u), uu));
                }
                if (mink2 < cut2k) {
                    if (nr == 8) {
                        // phase-recurrence fast path for one half
                        float bf = (float)b, cf2 = (float)cc;
                        if (half == 0) {
                            float Sc[9], Ss[9];
                            #pragma unroll
                            for (int t2 = 0; t2 < 9; t2++) { Sc[t2]=0.f; Ss[t2]=0.f; }
                            for (int i = lane; i < n; i += 32) {
                                float x=sx[i], y=sy[i], z=sz[i], qi=sq[i];
                                float th = bf*(R10*x + R11*y + R12*z)
                                         + cf2*(R20*x + R21*y + R22*z);
                                float sn, co; sincosf(th, &sn, &co);
                                float pr = qi*co, pim = qi*sn;
                                float ur = uc[i], ui = us[i];
                                Sc[0] += pr; Ss[0] += pim;
                                #pragma unroll
                                for (int a = 1; a <= 8; a++) {
                                    float t1 = pr*ur - pim*ui;
                                    pim = pr*ui + pim*ur; pr = t1;
                                    Sc[a] += pr; Ss[a] += pim;
                                }
                            }
                            #pragma unroll
                            for (int t2 = 0; t2 < 9; t2++) {
                                float scv = Sc[t2], ssv = Ss[t2];
                                #pragma unroll
                                for (int o = 16; o > 0; o >>= 1) {
                                    scv += __shfl_xor_sync(0xffffffffu, scv, o);
                                    ssv += __shfl_xor_sync(0xffffffffu, ssv, o);
                                }
                                if (lane == 0) {
                                    float af = (float)t2;
                                    float kx = af*R00+ux, ky = af*R01+uy, kz = af*R02+uz;
                                    float kl2 = kx*kx + ky*ky + kz*kz;
                                    if (kl2 > EPS2 && kl2 < cut2k)
                                        kacc += (double)(wt * __expf(-eta2h*kl2) / kl2
                                                         * (scv*scv + ssv*ssv));
                                }
                            }
                        } else {
                            float Sc[8], Ss[8];
                            #pragma unroll
                            for (int t2 = 0; t2 < 8; t2++) { Sc[t2]=0.f; Ss[t2]=0.f; }
                            for (int i = lane; i < n; i += 32) {
                                float x=sx[i], y=sy[i], z=sz[i], qi=sq[i];
                                float th = bf*(R10*x + R11*y + R12*z)
                                         + cf2*(R20*x + R21*y + R22*z);
                                float sn, co; sincosf(th, &sn, &co);
                                float pr = qi*co, pim = qi*sn;
                                float ur = uc[i], ui = us[i];   // multiply by conj each step
                                #pragma unroll
                                for (int a = 0; a < 8; a++) {
                                    float t1 = pr*ur + pim*ui;
                                    pim = pim*ur - pr*ui; pr = t1;
                                    Sc[a] += pr; Ss[a] += pim;
                                }
                            }
                            #pragma unroll
                            for (int t2 = 0; t2 < 8; t2++) {
                                float scv = Sc[t2], ssv = Ss[t2];
                                #pragma unroll
                                for (int o = 16; o > 0; o >>= 1) {
                                    scv += __shfl_xor_sync(0xffffffffu, scv, o);
                                    ssv += __shfl_xor_sync(0xffffffffu, ssv, o);
                                }
                                if (lane == 0) {
                                    float af = (float)(-(t2+1));
                                    float kx = af*R00+ux, ky = af*R01+uy, kz = af*R02+uz;
                                    float kl2 = kx*kx + ky*ky + kz*kz;
                                    if (kl2 > EPS2 && kl2 < cut2k)
                                        kacc += (double)(wt * __expf(-eta2h*kl2) / kl2
                                                         * (scv*scv + ssv*ssv));
                                }
                            }
                        }
                    } else {
                        for (int a = alo; a <= ahi; a++) {
                            float af = (float)a;
                            float kx = af*R00+ux, ky = af*R01+uy, kz = af*R02+uz;
                            float kl2 = kx*kx + ky*ky + kz*kz;
                            if (!(kl2 > EPS2 && kl2 < cut2k)) continue;
                            float scv = 0.f, ssv = 0.f;
                            for (int i = lane; i < n; i += 32) {
                                float th = kx*sx[i] + ky*sy[i] + kz*sz[i];
                                float sn, co; sincosf(th, &sn, &co);
                                scv = fmaf(sq[i], co, scv);
                                ssv = fmaf(sq[i], sn, ssv);
                            }
                            #pragma unroll
                            for (int o = 16; o > 0; o >>= 1) {
                                scv += __shfl_xor_sync(0xffffffffu, scv, o);
                                ssv += __shfl_xor_sync(0xffffffffu, ssv, o);
                            }
                            if (lane == 0)
                                kacc += (double)(wt * __expf(-eta2h*kl2) / kl2
                                                 * (scv*scv + ssv*ssv));
                        }
                    }
                }
            }
        } else {
            // ============ REAL: 256 pairs per unit ============
            long long p = (w - Urec)*256 + tid;
            if (p < T) {
                // decode upper-triangular (i,j), i<=j — float estimate + int fixup
                float tnf = 2.f*(float)n + 1.f;
                long long discl = (long long)(2*n+1)*(2*n+1) - 8*p;
                int i = (int)((tnf - sqrtf((float)discl)) * 0.5f);
                if (i < 0) i = 0;
                if (i >= n) i = n - 1;
                long long off = (long long)i*n - (long long)i*(i-1)/2;
                while (p < off) { i--; off = (long long)i*n - (long long)i*(i-1)/2; }
                while (p >= off + (long long)(n - i)) { off += (n - i); i++; }
                int j = i + (int)(p - off);

                float dx0 = sx[j]-sx[i], dy0 = sy[j]-sy[i], dz0 = sz[j]-sz[i];
                float gi = ssig[i], gj = ssig[j];
                float inv_s2gam = rsqrtf(2.f*(gi*gi + gj*gj));

                float sum = 0.f;
                if (P.fastR) {
                    // two smallest per-dim residuals -> 8 candidate images
                    float rx0 = dx0 - P.Ld[0]*rintf(dx0*P.invLd[0]);
                    float ry0 = dy0 - P.Ld[1]*rintf(dy0*P.invLd[1]);
                    float rz0 = dz0 - P.Ld[2]*rintf(dz0*P.invLd[2]);
                    float rx1 = rx0 - copysignf(P.Ld[0], rx0);
                    float ry1 = ry0 - copysignf(P.Ld[1], ry0);
                    float rz1 = rz0 - copysignf(P.Ld[2], rz0);
                    float ax0 = rx0*rx0, ax1 = rx1*rx1;
                    float ay0 = ry0*ry0, ay1 = ry1*ry1;
                    float az0 = rz0*rz0, az1 = rz1*rz1;
                    unsigned m = 0u;
                    #pragma unroll
                    for (int t = 0; t < 8; t++) {
                        float d2 = ((t&1)?ax1:ax0) + ((t&2)?ay1:ay0) + ((t&4)?az1:az0);
                        if (d2 > EPS2 && d2 < cut2r) m |= (1u << t);
                    }
                    while (m) {
                        int t = __ffs(m) - 1; m &= m - 1;
                        float d2 = ((t&1)?ax1:ax0) + ((t&2)?ay1:ay0) + ((t&4)?az1:az0);
                        float rd = rsqrtf(d2);
                        float dist = d2*rd;
                        float u1 = fminf(dist*inv_s2eta*TSCALE, TCLAMP);
                        float u2 = fminf(dist*inv_s2gam*TSCALE, TCLAMP);
                        int k1 = (int)u1, k2 = (int)u2;
                        float2 e1 = stab[k1], e2 = stab[k2];
                        float v1 = fmaf(u1-(float)k1, e1.y, e1.x);
                        float v2 = fmaf(u2-(float)k2, e2.y, e2.x);
                        sum = fmaf(v1 - v2, rd, sum);
                    }
                } else {
                    // generic cell fallback: shifts on the fly
                    int two = P.twoR, nrr = P.nrr, nsh = P.nsh;
                    for (int s = 0; s < nsh; s++) {
                        int a = s/(two*two) - nrr;
                        int r2 = s%(two*two);
                        int b = r2/two - nrr;
                        int c3 = r2%two - nrr;
                        float dx = dx0 + a*P.cf[0] + b*P.cf[3] + c3*P.cf[6];
                        float dy = dy0 + a*P.cf[1] + b*P.cf[4] + c3*P.cf[7];
                        float dz = dz0 + a*P.cf[2] + b*P.cf[5] + c3*P.cf[8];
                        float d2 = fmaf(dx,dx, fmaf(dy,dy, dz*dz));
                        if (d2 > EPS2 && d2 < cut2r) {
                            float rd = rsqrtf(d2);
                            float dist = d2*rd;
                            float u1 = fminf(dist*inv_s2eta*TSCALE, TCLAMP);
                            float u2 = fminf(dist*inv_s2gam*TSCALE, TCLAMP);
                            int k1 = (int)u1, k2 = (int)u2;
                            float2 e1 = stab[k1], e2 = stab[k2];
                            float v1 = fmaf(u1-(float)k1, e1.y, e1.x);
                            float v2 = fmaf(u2-(float)k2, e2.y, e2.x);
                            sum = fmaf(v1 - v2, rd, sum);
                        }
                    }
                }
                float wq = sq[i]*sq[j];
                if (i == j) racc += (double)(wq*(sum + self_c + 1.f/(SQRTPI*gi)));
                else        racc += (double)(2.f*wq*sum);
            }
        }
    }

    double tot = 0.5*COEF*(racc + (double)P.pref4 * kacc);
    sred[tid] = tot;
    __syncthreads();
    for (int s = 128; s > 0; s >>= 1) {
        if (tid < s) sred[tid] += sred[tid + s];
        __syncthreads();
    }
    if (tid == 0) {
        atomicAdd(&g_acc, sred[0]);
        __threadfence();
        unsigned t = atomicAdd(&g_done, 1u);
        if (t == gridDim.x - 1) {
            double v = atomicAdd(&g_acc, 0.0);
            out[0] = (float)v;
            g_acc = 0.0;
            g_done = 0u;
        }
    }
}

extern "C" void kernel_launch(void* const* d_in, const int* in_sizes, int n_in,
                              void* d_out, int out_size)
{
    const float* pos     = (const float*)d_in[0];
    const float* cell    = (const float*)d_in[1];
    const float* charges = (const float*)d_in[2];
    const float* sigt    = (const float*)d_in[3];
    const int*   spec    = (const int*)d_in[4];
    const int*   nsr     = (const int*)d_in[5];
    const int*   nsk     = (const int*)d_in[6];
    int n = in_sizes[0] / 3;

    ewald_fused_kernel<<<444, 256>>>(pos, cell, charges, sigt, spec, nsr, nsk,
                                     (float*)d_out, n);
}